// round 2
// baseline (speedup 1.0000x reference)
#include <cuda_runtime.h>
#include <cuda_bf16.h>
#include <math.h>
#include <stdint.h>

// ---------------- problem constants ----------------
#define D_MODEL 1024
#define D_INNER 2048
#define NBATCH  4
#define SEQ_T   4096
#define M_TOK   (NBATCH * SEQ_T)     // 16384 tokens
#define N1      (2 * D_INNER)        // 4096 (in_proj out)
#define K1      D_MODEL              // 1024
#define N2      D_MODEL              // 1024 (out_proj out)
#define K2      D_INNER              // 2048
#define LN_EPS  1e-5f

// ---------------- scratch (static device arrays; no allocs) ----------------
__device__ __nv_bfloat16 g_xn_hi[(size_t)M_TOK * D_MODEL];
__device__ __nv_bfloat16 g_xn_lo[(size_t)M_TOK * D_MODEL];
__device__ __nv_bfloat16 g_win_hi[(size_t)N1 * K1];
__device__ __nv_bfloat16 g_win_lo[(size_t)N1 * K1];
__device__ __nv_bfloat16 g_wout_hi[(size_t)N2 * K2];
__device__ __nv_bfloat16 g_wout_lo[(size_t)N2 * K2];
__device__ float         g_xz[(size_t)M_TOK * N1];          // 256 MB
__device__ __nv_bfloat16 g_y_hi[(size_t)M_TOK * D_INNER];
__device__ __nv_bfloat16 g_y_lo[(size_t)M_TOK * D_INNER];

// ---------------- helpers ----------------
__device__ __forceinline__ void split_bf16(float v, __nv_bfloat16& h, __nv_bfloat16& l) {
    h = __float2bfloat16(v);
    l = __float2bfloat16(v - __bfloat162float(h));
}

__global__ __launch_bounds__(256) void split_kernel(
    const float* __restrict__ w, __nv_bfloat16* __restrict__ hi,
    __nv_bfloat16* __restrict__ lo, int n)
{
    int i = blockIdx.x * 256 + threadIdx.x;
    if (i < n) {
        float v = w[i];
        __nv_bfloat16 h, l;
        split_bf16(v, h, l);
        hi[i] = h; lo[i] = l;
    }
}

// ---------------- LayerNorm + bf16 hi/lo split ----------------
__global__ __launch_bounds__(256) void ln_split_kernel(
    const float* __restrict__ x, const float* __restrict__ gamma,
    const float* __restrict__ beta,
    __nv_bfloat16* __restrict__ xh, __nv_bfloat16* __restrict__ xl)
{
    int row = blockIdx.x;
    int tid = threadIdx.x;
    const float4 v = reinterpret_cast<const float4*>(x + (size_t)row * D_MODEL)[tid];
    float s  = v.x + v.y + v.z + v.w;
    float ss = v.x*v.x + v.y*v.y + v.z*v.z + v.w*v.w;
    #pragma unroll
    for (int o = 16; o; o >>= 1) {
        s  += __shfl_xor_sync(0xffffffffu, s,  o);
        ss += __shfl_xor_sync(0xffffffffu, ss, o);
    }
    __shared__ float rs[8], rq[8], mv[2];
    int wid = tid >> 5, lane = tid & 31;
    if (lane == 0) { rs[wid] = s; rq[wid] = ss; }
    __syncthreads();
    if (tid == 0) {
        float a = 0.f, b = 0.f;
        #pragma unroll
        for (int i = 0; i < 8; i++) { a += rs[i]; b += rq[i]; }
        float mu  = a * (1.f / D_MODEL);
        float var = b * (1.f / D_MODEL) - mu * mu;
        mv[0] = mu; mv[1] = rsqrtf(var + LN_EPS);
    }
    __syncthreads();
    float mu = mv[0], rstd = mv[1];
    float vv[4] = {v.x, v.y, v.z, v.w};
    int c0 = tid * 4;
    #pragma unroll
    for (int j = 0; j < 4; j++) {
        int c = c0 + j;
        float xn = (vv[j] - mu) * rstd * gamma[c] + beta[c];
        __nv_bfloat16 h, l;
        split_bf16(xn, h, l);
        size_t o = (size_t)row * D_MODEL + c;
        xh[o] = h; xl[o] = l;
    }
}

// ---------------- depthwise causal conv + SiLU gate + split ----------------
__global__ __launch_bounds__(256) void conv_gate_kernel(
    const float* __restrict__ xz, const float* __restrict__ cw,
    const float* __restrict__ cb,
    __nv_bfloat16* __restrict__ yh, __nv_bfloat16* __restrict__ yl)
{
    int id = blockIdx.x * 256 + threadIdx.x;   // over M_TOK * D_INNER = 33.5M
    int c = id & (D_INNER - 1);
    int m = id >> 11;                          // token index (b*T + t)
    int t = m & (SEQ_T - 1);
    size_t base = (size_t)m * N1 + c;          // x_part column c, row m
    float acc = cb[c];
    #pragma unroll
    for (int j = 0; j < 4; j++) {
        int tt = t - 3 + j;
        if (tt >= 0) acc += cw[c * 4 + j] * xz[base - (size_t)(3 - j) * N1];
    }
    float z = xz[base + D_INNER];
    float sa = acc / (1.f + expf(-acc));
    float sz = z   / (1.f + expf(-z));
    float y = sa * sz;
    __nv_bfloat16 h, l;
    split_bf16(y, h, l);
    yh[id] = h; yl[id] = l;
}

// ---------------- bf16x3 GEMM: C[M,N] = A[M,K] * B[N,K]^T (+ residual) ------
// Tiles: 128x128x32, 256 threads (8 warps as 2x4, warp tile 64x32), cp.async
// 2-stage pipeline, ldmatrix with 40-element row stride (conflict-free).

#define BK          32
#define SM_STRIDE   40                          // bf16 elements per smem row
#define ARR_BYTES   (128 * SM_STRIDE * 2)       // 10240
#define STAGE_BYTES (4 * ARR_BYTES)             // 40960

#define LDSM4(R0, R1, R2, R3, ADDR)                                         \
    asm volatile("ldmatrix.sync.aligned.m8n8.x4.shared.b16 {%0,%1,%2,%3},[%4];" \
                 : "=r"(R0), "=r"(R1), "=r"(R2), "=r"(R3) : "r"(ADDR))

#define MMA16816(C, A, B0, B1)                                              \
    asm volatile("mma.sync.aligned.m16n8k16.row.col.f32.bf16.bf16.f32 "      \
                 "{%0,%1,%2,%3},{%4,%5,%6,%7},{%8,%9},{%0,%1,%2,%3};"        \
                 : "+f"((C)[0]), "+f"((C)[1]), "+f"((C)[2]), "+f"((C)[3])    \
                 : "r"((A)[0]), "r"((A)[1]), "r"((A)[2]), "r"((A)[3]),       \
                   "r"(B0), "r"(B1))

template <bool ADD_RES>
__global__ __launch_bounds__(256) void gemm_bf16x3(
    const __nv_bfloat16* __restrict__ A_hi, const __nv_bfloat16* __restrict__ A_lo,
    const __nv_bfloat16* __restrict__ B_hi, const __nv_bfloat16* __restrict__ B_lo,
    float* __restrict__ C, const float* __restrict__ R, int K, int Nn)
{
    extern __shared__ __align__(16) char smem[];
    const uint32_t sbase = (uint32_t)__cvta_generic_to_shared(smem);
    const int tid = threadIdx.x;
    const int bm = blockIdx.y, bn = blockIdx.x;
    const int nk = K >> 5;

    const __nv_bfloat16* gA[2] = {A_hi + (size_t)bm * 128 * K,
                                  A_lo + (size_t)bm * 128 * K};
    const __nv_bfloat16* gB[2] = {B_hi + (size_t)bn * 128 * K,
                                  B_lo + (size_t)bn * 128 * K};

    float acc[4][4][4];
    #pragma unroll
    for (int a = 0; a < 4; a++)
        #pragma unroll
        for (int b = 0; b < 4; b++)
            #pragma unroll
            for (int c = 0; c < 4; c++) acc[a][b][c] = 0.f;

    auto load_stage = [&](int s, int kt) {
        #pragma unroll
        for (int arr = 0; arr < 4; arr++) {
            const __nv_bfloat16* gp = (arr < 2) ? gA[arr] : gB[arr - 2];
            uint32_t so = sbase + s * STAGE_BYTES + arr * ARR_BYTES;
            #pragma unroll
            for (int rep = 0; rep < 2; rep++) {
                int ch = rep * 256 + tid;
                int r = ch >> 2, cc = (ch & 3) * 8;
                const __nv_bfloat16* src = gp + (size_t)r * K + kt * BK + cc;
                uint32_t dst = so + (uint32_t)(r * SM_STRIDE + cc) * 2u;
                asm volatile("cp.async.cg.shared.global [%0], [%1], 16;\n"
                             :: "r"(dst), "l"(src));
            }
        }
    };

    const int wid = tid >> 5, lane = tid & 31;
    const int wm = (wid >> 2) << 6;   // 0 / 64
    const int wn = (wid & 3) << 5;    // 0..96

    auto compute = [&](int s) {
        uint32_t base = sbase + s * STAGE_BYTES;
        #pragma unroll
        for (int ks = 0; ks < 2; ks++) {
            uint32_t ah[4][4], al[4][4], bh[4][2], bl[4][2];
            int arow = wm + (lane & 15);
            int acol = ks * 16 + (lane >> 4) * 8;
            #pragma unroll
            for (int mi = 0; mi < 4; mi++) {
                uint32_t ad = base + (uint32_t)(((arow + mi * 16) * SM_STRIDE + acol) << 1);
                LDSM4(ah[mi][0], ah[mi][1], ah[mi][2], ah[mi][3], ad);
                LDSM4(al[mi][0], al[mi][1], al[mi][2], al[mi][3], ad + ARR_BYTES);
            }
            int brow = wn + ((lane >> 4) & 1) * 8 + (lane & 7);
            int bcol = ks * 16 + ((lane >> 3) & 1) * 8;
            #pragma unroll
            for (int p = 0; p < 2; p++) {
                uint32_t bd = base + 2 * ARR_BYTES +
                              (uint32_t)(((brow + p * 16) * SM_STRIDE + bcol) << 1);
                uint32_t r0, r1, r2, r3;
                LDSM4(r0, r1, r2, r3, bd);
                bh[2 * p][0] = r0; bh[2 * p][1] = r1;
                bh[2 * p + 1][0] = r2; bh[2 * p + 1][1] = r3;
                LDSM4(r0, r1, r2, r3, bd + ARR_BYTES);
                bl[2 * p][0] = r0; bl[2 * p][1] = r1;
                bl[2 * p + 1][0] = r2; bl[2 * p + 1][1] = r3;
            }
            #pragma unroll
            for (int mi = 0; mi < 4; mi++)
                #pragma unroll
                for (int ni = 0; ni < 4; ni++) {
                    MMA16816(acc[mi][ni], ah[mi], bh[ni][0], bh[ni][1]);
                    MMA16816(acc[mi][ni], ah[mi], bl[ni][0], bl[ni][1]);
                    MMA16816(acc[mi][ni], al[mi], bh[ni][0], bh[ni][1]);
                }
        }
    };

    load_stage(0, 0);
    asm volatile("cp.async.commit_group;");
    for (int kt = 0; kt < nk; kt++) {
        if (kt + 1 < nk) load_stage((kt + 1) & 1, kt + 1);
        asm volatile("cp.async.commit_group;");
        asm volatile("cp.async.wait_group 1;");
        __syncthreads();
        compute(kt & 1);
        __syncthreads();
    }

    // epilogue
    const int g = lane >> 2, tq = (lane & 3) * 2;
    #pragma unroll
    for (int mi = 0; mi < 4; mi++)
        #pragma unroll
        for (int ni = 0; ni < 4; ni++) {
            int row = bm * 128 + wm + mi * 16 + g;
            int col = bn * 128 + wn + ni * 8 + tq;
            float2 v0 = make_float2(acc[mi][ni][0], acc[mi][ni][1]);
            float2 v1 = make_float2(acc[mi][ni][2], acc[mi][ni][3]);
            if (ADD_RES) {
                float2 r0 = *reinterpret_cast<const float2*>(R + (size_t)row * Nn + col);
                float2 r1 = *reinterpret_cast<const float2*>(R + (size_t)(row + 8) * Nn + col);
                v0.x += r0.x; v0.y += r0.y;
                v1.x += r1.x; v1.y += r1.y;
            }
            *reinterpret_cast<float2*>(C + (size_t)row * Nn + col) = v0;
            *reinterpret_cast<float2*>(C + (size_t)(row + 8) * Nn + col) = v1;
        }
}

// ---------------- launch ----------------
extern "C" void kernel_launch(void* const* d_in, const int* in_sizes, int n_in,
                              void* d_out, int out_size)
{
    const float* x     = (const float*)d_in[0];
    const float* gamma = (const float*)d_in[1];
    const float* beta  = (const float*)d_in[2];
    const float* W_in  = (const float*)d_in[3];
    const float* cw    = (const float*)d_in[4];
    const float* cb    = (const float*)d_in[5];
    const float* W_out = (const float*)d_in[6];
    float* out = (float*)d_out;

    void *p_xnh, *p_xnl, *p_winh, *p_winl, *p_wouth, *p_woutl, *p_xz, *p_yh, *p_yl;
    cudaGetSymbolAddress(&p_xnh,  g_xn_hi);
    cudaGetSymbolAddress(&p_xnl,  g_xn_lo);
    cudaGetSymbolAddress(&p_winh, g_win_hi);
    cudaGetSymbolAddress(&p_winl, g_win_lo);
    cudaGetSymbolAddress(&p_wouth, g_wout_hi);
    cudaGetSymbolAddress(&p_woutl, g_wout_lo);
    cudaGetSymbolAddress(&p_xz,   g_xz);
    cudaGetSymbolAddress(&p_yh,   g_y_hi);
    cudaGetSymbolAddress(&p_yl,   g_y_lo);

    cudaFuncSetAttribute(gemm_bf16x3<false>,
        cudaFuncAttributeMaxDynamicSharedMemorySize, 2 * STAGE_BYTES);
    cudaFuncSetAttribute(gemm_bf16x3<true>,
        cudaFuncAttributeMaxDynamicSharedMemorySize, 2 * STAGE_BYTES);

    // weight splits (cheap, deterministic)
    split_kernel<<<(N1 * K1 + 255) / 256, 256>>>(W_in,
        (__nv_bfloat16*)p_winh, (__nv_bfloat16*)p_winl, N1 * K1);
    split_kernel<<<(N2 * K2 + 255) / 256, 256>>>(W_out,
        (__nv_bfloat16*)p_wouth, (__nv_bfloat16*)p_woutl, N2 * K2);

    // LayerNorm + split
    ln_split_kernel<<<M_TOK, 256>>>(x, gamma, beta,
        (__nv_bfloat16*)p_xnh, (__nv_bfloat16*)p_xnl);

    // GEMM1: xz = xn @ W_in^T   [16384 x 4096]
    dim3 g1(N1 / 128, M_TOK / 128);
    gemm_bf16x3<false><<<g1, 256, 2 * STAGE_BYTES>>>(
        (const __nv_bfloat16*)p_xnh, (const __nv_bfloat16*)p_xnl,
        (const __nv_bfloat16*)p_winh, (const __nv_bfloat16*)p_winl,
        (float*)p_xz, nullptr, K1, N1);

    // conv + gate + split
    conv_gate_kernel<<<(M_TOK * D_INNER) / 256, 256>>>(
        (const float*)p_xz, cw, cb,
        (__nv_bfloat16*)p_yh, (__nv_bfloat16*)p_yl);

    // GEMM2 + residual: out = x + y @ W_out^T   [16384 x 1024]
    dim3 g2(N2 / 128, M_TOK / 128);
    gemm_bf16x3<true><<<g2, 256, 2 * STAGE_BYTES>>>(
        (const __nv_bfloat16*)p_yh, (const __nv_bfloat16*)p_yl,
        (const __nv_bfloat16*)p_wouth, (const __nv_bfloat16*)p_woutl,
        out, x, K2, N2);
}

// round 3
// speedup vs baseline: 1.0015x; 1.0015x over previous
#include <cuda_runtime.h>
#include <cuda_bf16.h>
#include <math.h>
#include <stdint.h>

// ---------------- problem constants ----------------
#define D_MODEL 1024
#define D_INNER 2048
#define NBATCH  4
#define SEQ_T   4096
#define M_TOK   (NBATCH * SEQ_T)     // 16384 tokens
#define N1      (2 * D_INNER)        // 4096 (in_proj out)
#define K1      D_MODEL              // 1024
#define N2      D_MODEL              // 1024 (out_proj out)
#define K2      D_INNER              // 2048
#define LN_EPS  1e-5f

// ---------------- scratch (static device arrays; no allocs) ----------------
__device__ __nv_bfloat16 g_xn_hi[(size_t)M_TOK * D_MODEL];
__device__ __nv_bfloat16 g_xn_lo[(size_t)M_TOK * D_MODEL];
__device__ __nv_bfloat16 g_win_hi[(size_t)N1 * K1];
__device__ __nv_bfloat16 g_win_lo[(size_t)N1 * K1];
__device__ __nv_bfloat16 g_wout_hi[(size_t)N2 * K2];
__device__ __nv_bfloat16 g_wout_lo[(size_t)N2 * K2];
__device__ float         g_xz[(size_t)M_TOK * N1];          // 256 MB
__device__ __nv_bfloat16 g_y_hi[(size_t)M_TOK * D_INNER];
__device__ __nv_bfloat16 g_y_lo[(size_t)M_TOK * D_INNER];

// ---------------- helpers ----------------
__device__ __forceinline__ void split_bf16(float v, __nv_bfloat16& h, __nv_bfloat16& l) {
    h = __float2bfloat16(v);
    l = __float2bfloat16(v - __bfloat162float(h));
}

__global__ __launch_bounds__(256) void split_kernel(
    const float* __restrict__ w, __nv_bfloat16* __restrict__ hi,
    __nv_bfloat16* __restrict__ lo, int n)
{
    int i = blockIdx.x * 256 + threadIdx.x;
    if (i < n) {
        float v = w[i];
        __nv_bfloat16 h, l;
        split_bf16(v, h, l);
        hi[i] = h; lo[i] = l;
    }
}

// ---------------- LayerNorm + bf16 hi/lo split ----------------
__global__ __launch_bounds__(256) void ln_split_kernel(
    const float* __restrict__ x, const float* __restrict__ gamma,
    const float* __restrict__ beta,
    __nv_bfloat16* __restrict__ xh, __nv_bfloat16* __restrict__ xl)
{
    int row = blockIdx.x;
    int tid = threadIdx.x;
    const float4 v = reinterpret_cast<const float4*>(x + (size_t)row * D_MODEL)[tid];
    float s  = v.x + v.y + v.z + v.w;
    float ss = v.x*v.x + v.y*v.y + v.z*v.z + v.w*v.w;
    #pragma unroll
    for (int o = 16; o; o >>= 1) {
        s  += __shfl_xor_sync(0xffffffffu, s,  o);
        ss += __shfl_xor_sync(0xffffffffu, ss, o);
    }
    __shared__ float rs[8], rq[8], mv[2];
    int wid = tid >> 5, lane = tid & 31;
    if (lane == 0) { rs[wid] = s; rq[wid] = ss; }
    __syncthreads();
    if (tid == 0) {
        float a = 0.f, b = 0.f;
        #pragma unroll
        for (int i = 0; i < 8; i++) { a += rs[i]; b += rq[i]; }
        float mu  = a * (1.f / D_MODEL);
        float var = b * (1.f / D_MODEL) - mu * mu;
        mv[0] = mu; mv[1] = rsqrtf(var + LN_EPS);
    }
    __syncthreads();
    float mu = mv[0], rstd = mv[1];
    float vv[4] = {v.x, v.y, v.z, v.w};
    int c0 = tid * 4;
    #pragma unroll
    for (int j = 0; j < 4; j++) {
        int c = c0 + j;
        float xn = (vv[j] - mu) * rstd * gamma[c] + beta[c];
        __nv_bfloat16 h, l;
        split_bf16(xn, h, l);
        size_t o = (size_t)row * D_MODEL + c;
        xh[o] = h; xl[o] = l;
    }
}

// ---------------- depthwise causal conv + SiLU gate + split ----------------
__global__ __launch_bounds__(256) void conv_gate_kernel(
    const float* __restrict__ xz, const float* __restrict__ cw,
    const float* __restrict__ cb,
    __nv_bfloat16* __restrict__ yh, __nv_bfloat16* __restrict__ yl)
{
    int id = blockIdx.x * 256 + threadIdx.x;   // over M_TOK * D_INNER = 33.5M
    int c = id & (D_INNER - 1);
    int m = id >> 11;                          // token index (b*T + t)
    int t = m & (SEQ_T - 1);
    size_t base = (size_t)m * N1 + c;          // x_part column c, row m
    float acc = cb[c];
    #pragma unroll
    for (int j = 0; j < 4; j++) {
        int tt = t - 3 + j;
        if (tt >= 0) acc += cw[c * 4 + j] * xz[base - (size_t)(3 - j) * N1];
    }
    float z = xz[base + D_INNER];
    float sa = acc / (1.f + expf(-acc));
    float sz = z   / (1.f + expf(-z));
    float y = sa * sz;
    __nv_bfloat16 h, l;
    split_bf16(y, h, l);
    yh[id] = h; yl[id] = l;
}

// ---------------- bf16x3 GEMM: C[M,N] = A[M,K] * B[N,K]^T (+ residual) ------
// Tiles: 128x128x32, 256 threads (8 warps as 2x4, warp tile 64x32), cp.async
// 2-stage pipeline, ldmatrix with 40-element row stride (conflict-free).

#define BK          32
#define SM_STRIDE   40                          // bf16 elements per smem row
#define ARR_BYTES   (128 * SM_STRIDE * 2)       // 10240
#define STAGE_BYTES (4 * ARR_BYTES)             // 40960

#define LDSM4(R0, R1, R2, R3, ADDR)                                         \
    asm volatile("ldmatrix.sync.aligned.m8n8.x4.shared.b16 {%0,%1,%2,%3},[%4];" \
                 : "=r"(R0), "=r"(R1), "=r"(R2), "=r"(R3) : "r"(ADDR))

#define MMA16816(C, A, B0, B1)                                              \
    asm volatile("mma.sync.aligned.m16n8k16.row.col.f32.bf16.bf16.f32 "      \
                 "{%0,%1,%2,%3},{%4,%5,%6,%7},{%8,%9},{%0,%1,%2,%3};"        \
                 : "+f"((C)[0]), "+f"((C)[1]), "+f"((C)[2]), "+f"((C)[3])    \
                 : "r"((A)[0]), "r"((A)[1]), "r"((A)[2]), "r"((A)[3]),       \
                   "r"(B0), "r"(B1))

template <bool ADD_RES>
__global__ __launch_bounds__(256) void gemm_bf16x3(
    const __nv_bfloat16* __restrict__ A_hi, const __nv_bfloat16* __restrict__ A_lo,
    const __nv_bfloat16* __restrict__ B_hi, const __nv_bfloat16* __restrict__ B_lo,
    float* __restrict__ C, const float* __restrict__ R, int K, int Nn)
{
    extern __shared__ __align__(16) char smem[];
    const uint32_t sbase = (uint32_t)__cvta_generic_to_shared(smem);
    const int tid = threadIdx.x;
    const int bm = blockIdx.y, bn = blockIdx.x;
    const int nk = K >> 5;

    const __nv_bfloat16* gA[2] = {A_hi + (size_t)bm * 128 * K,
                                  A_lo + (size_t)bm * 128 * K};
    const __nv_bfloat16* gB[2] = {B_hi + (size_t)bn * 128 * K,
                                  B_lo + (size_t)bn * 128 * K};

    float acc[4][4][4];
    #pragma unroll
    for (int a = 0; a < 4; a++)
        #pragma unroll
        for (int b = 0; b < 4; b++)
            #pragma unroll
            for (int c = 0; c < 4; c++) acc[a][b][c] = 0.f;

    auto load_stage = [&](int s, int kt) {
        #pragma unroll
        for (int arr = 0; arr < 4; arr++) {
            const __nv_bfloat16* gp = (arr < 2) ? gA[arr] : gB[arr - 2];
            uint32_t so = sbase + s * STAGE_BYTES + arr * ARR_BYTES;
            #pragma unroll
            for (int rep = 0; rep < 2; rep++) {
                int ch = rep * 256 + tid;
                int r = ch >> 2, cc = (ch & 3) * 8;
                const __nv_bfloat16* src = gp + (size_t)r * K + kt * BK + cc;
                uint32_t dst = so + (uint32_t)(r * SM_STRIDE + cc) * 2u;
                asm volatile("cp.async.cg.shared.global [%0], [%1], 16;\n"
                             :: "r"(dst), "l"(src));
            }
        }
    };

    const int wid = tid >> 5, lane = tid & 31;
    const int wm = (wid >> 2) << 6;   // 0 / 64
    const int wn = (wid & 3) << 5;    // 0..96

    auto compute = [&](int s) {
        uint32_t base = sbase + s * STAGE_BYTES;
        #pragma unroll
        for (int ks = 0; ks < 2; ks++) {
            uint32_t ah[4][4], al[4][4], bh[4][2], bl[4][2];
            int arow = wm + (lane & 15);
            int acol = ks * 16 + (lane >> 4) * 8;
            #pragma unroll
            for (int mi = 0; mi < 4; mi++) {
                uint32_t ad = base + (uint32_t)(((arow + mi * 16) * SM_STRIDE + acol) << 1);
                LDSM4(ah[mi][0], ah[mi][1], ah[mi][2], ah[mi][3], ad);
                LDSM4(al[mi][0], al[mi][1], al[mi][2], al[mi][3], ad + ARR_BYTES);
            }
            int brow = wn + ((lane >> 4) & 1) * 8 + (lane & 7);
            int bcol = ks * 16 + ((lane >> 3) & 1) * 8;
            #pragma unroll
            for (int p = 0; p < 2; p++) {
                uint32_t bd = base + 2 * ARR_BYTES +
                              (uint32_t)(((brow + p * 16) * SM_STRIDE + bcol) << 1);
                uint32_t r0, r1, r2, r3;
                LDSM4(r0, r1, r2, r3, bd);
                bh[2 * p][0] = r0; bh[2 * p][1] = r1;
                bh[2 * p + 1][0] = r2; bh[2 * p + 1][1] = r3;
                LDSM4(r0, r1, r2, r3, bd + ARR_BYTES);
                bl[2 * p][0] = r0; bl[2 * p][1] = r1;
                bl[2 * p + 1][0] = r2; bl[2 * p + 1][1] = r3;
            }
            #pragma unroll
            for (int mi = 0; mi < 4; mi++)
                #pragma unroll
                for (int ni = 0; ni < 4; ni++) {
                    MMA16816(acc[mi][ni], ah[mi], bh[ni][0], bh[ni][1]);
                    MMA16816(acc[mi][ni], ah[mi], bl[ni][0], bl[ni][1]);
                    MMA16816(acc[mi][ni], al[mi], bh[ni][0], bh[ni][1]);
                }
        }
    };

    load_stage(0, 0);
    asm volatile("cp.async.commit_group;");
    for (int kt = 0; kt < nk; kt++) {
        if (kt + 1 < nk) load_stage((kt + 1) & 1, kt + 1);
        asm volatile("cp.async.commit_group;");
        asm volatile("cp.async.wait_group 1;");
        __syncthreads();
        compute(kt & 1);
        __syncthreads();
    }

    // epilogue
    const int g = lane >> 2, tq = (lane & 3) * 2;
    #pragma unroll
    for (int mi = 0; mi < 4; mi++)
        #pragma unroll
        for (int ni = 0; ni < 4; ni++) {
            int row = bm * 128 + wm + mi * 16 + g;
            int col = bn * 128 + wn + ni * 8 + tq;
            float2 v0 = make_float2(acc[mi][ni][0], acc[mi][ni][1]);
            float2 v1 = make_float2(acc[mi][ni][2], acc[mi][ni][3]);
            if (ADD_RES) {
                float2 r0 = *reinterpret_cast<const float2*>(R + (size_t)row * Nn + col);
                float2 r1 = *reinterpret_cast<const float2*>(R + (size_t)(row + 8) * Nn + col);
                v0.x += r0.x; v0.y += r0.y;
                v1.x += r1.x; v1.y += r1.y;
            }
            *reinterpret_cast<float2*>(C + (size_t)row * Nn + col) = v0;
            *reinterpret_cast<float2*>(C + (size_t)(row + 8) * Nn + col) = v1;
        }
}

// ---------------- launch ----------------
extern "C" void kernel_launch(void* const* d_in, const int* in_sizes, int n_in,
                              void* d_out, int out_size)
{
    const float* x     = (const float*)d_in[0];
    const float* gamma = (const float*)d_in[1];
    const float* beta  = (const float*)d_in[2];
    const float* W_in  = (const float*)d_in[3];
    const float* cw    = (const float*)d_in[4];
    const float* cb    = (const float*)d_in[5];
    const float* W_out = (const float*)d_in[6];
    float* out = (float*)d_out;

    void *p_xnh, *p_xnl, *p_winh, *p_winl, *p_wouth, *p_woutl, *p_xz, *p_yh, *p_yl;
    cudaGetSymbolAddress(&p_xnh,  g_xn_hi);
    cudaGetSymbolAddress(&p_xnl,  g_xn_lo);
    cudaGetSymbolAddress(&p_winh, g_win_hi);
    cudaGetSymbolAddress(&p_winl, g_win_lo);
    cudaGetSymbolAddress(&p_wouth, g_wout_hi);
    cudaGetSymbolAddress(&p_woutl, g_wout_lo);
    cudaGetSymbolAddress(&p_xz,   g_xz);
    cudaGetSymbolAddress(&p_yh,   g_y_hi);
    cudaGetSymbolAddress(&p_yl,   g_y_lo);

    cudaFuncSetAttribute(gemm_bf16x3<false>,
        cudaFuncAttributeMaxDynamicSharedMemorySize, 2 * STAGE_BYTES);
    cudaFuncSetAttribute(gemm_bf16x3<true>,
        cudaFuncAttributeMaxDynamicSharedMemorySize, 2 * STAGE_BYTES);

    // weight splits (cheap, deterministic)
    split_kernel<<<(N1 * K1 + 255) / 256, 256>>>(W_in,
        (__nv_bfloat16*)p_winh, (__nv_bfloat16*)p_winl, N1 * K1);
    split_kernel<<<(N2 * K2 + 255) / 256, 256>>>(W_out,
        (__nv_bfloat16*)p_wouth, (__nv_bfloat16*)p_woutl, N2 * K2);

    // LayerNorm + split
    ln_split_kernel<<<M_TOK, 256>>>(x, gamma, beta,
        (__nv_bfloat16*)p_xnh, (__nv_bfloat16*)p_xnl);

    // GEMM1: xz = xn @ W_in^T   [16384 x 4096]
    dim3 g1(N1 / 128, M_TOK / 128);
    gemm_bf16x3<false><<<g1, 256, 2 * STAGE_BYTES>>>(
        (const __nv_bfloat16*)p_xnh, (const __nv_bfloat16*)p_xnl,
        (const __nv_bfloat16*)p_winh, (const __nv_bfloat16*)p_winl,
        (float*)p_xz, nullptr, K1, N1);

    // conv + gate + split
    conv_gate_kernel<<<(M_TOK * D_INNER) / 256, 256>>>(
        (const float*)p_xz, cw, cb,
        (__nv_bfloat16*)p_yh, (__nv_bfloat16*)p_yl);

    // GEMM2 + residual: out = x + y @ W_out^T   [16384 x 1024]
    dim3 g2(N2 / 128, M_TOK / 128);
    gemm_bf16x3<true><<<g2, 256, 2 * STAGE_BYTES>>>(
        (const __nv_bfloat16*)p_yh, (const __nv_bfloat16*)p_yl,
        (const __nv_bfloat16*)p_wouth, (const __nv_bfloat16*)p_woutl,
        out, x, K2, N2);
}

// round 5
// speedup vs baseline: 2.3813x; 2.3777x over previous
#include <cuda_runtime.h>
#include <cuda_fp16.h>
#include <math.h>
#include <stdint.h>

#define D_MODEL 1024
#define D_INNER 2048
#define M_TOK   16384
#define N1      4096
#define K1      1024
#define N2      1024
#define K2      2048
#define LN_EPS  1e-5f

__device__ __half g_xn  [(size_t)M_TOK * K1];
__device__ __half g_win [(size_t)N1 * K1];
__device__ __half g_wout[(size_t)N2 * K2];
__device__ __half g_xz  [(size_t)M_TOK * N1];
__device__ __half g_y   [(size_t)M_TOK * K2];

// ---------------- fp16 GEMM: C[M,N] = A[M,K] * B[N,K]^T ----------------
// 128x128x32 tiles, 256 thr (8 warps 2x4, warp 64x32), 3-stage cp.async,
// ldmatrix row stride 40 halves (conflict-free). f32 accum.
#define BK          32
#define SM_STRIDE   40
#define ARR_BYTES   (128 * SM_STRIDE * 2)   // 10240
#define STAGE_BYTES (2 * ARR_BYTES)         // 20480 (A + B)
#define SMEM_DYN    (3 * STAGE_BYTES)       // 61440

#define LDSM4(R0, R1, R2, R3, ADDR)                                          \
    asm volatile("ldmatrix.sync.aligned.m8n8.x4.shared.b16 {%0,%1,%2,%3},[%4];" \
                 : "=r"(R0), "=r"(R1), "=r"(R2), "=r"(R3) : "r"(ADDR))
#define MMA16816(C, A, B0, B1)                                               \
    asm volatile("mma.sync.aligned.m16n8k16.row.col.f32.f16.f16.f32 "         \
                 "{%0,%1,%2,%3},{%4,%5,%6,%7},{%8,%9},{%0,%1,%2,%3};"         \
                 : "+f"((C)[0]), "+f"((C)[1]), "+f"((C)[2]), "+f"((C)[3])     \
                 : "r"((A)[0]), "r"((A)[1]), "r"((A)[2]), "r"((A)[3]),        \
                   "r"(B0), "r"(B1))
#define CP16(dst, src) \
    asm volatile("cp.async.cg.shared.global [%0], [%1], 16;" :: "r"(dst), "l"(src))

template <bool OUT_HALF>
__global__ __launch_bounds__(256, 2) void gemm_f16(
    const __half* __restrict__ A, const __half* __restrict__ B,
    void* __restrict__ Cv, const float* __restrict__ R, int K, int Nn)
{
    extern __shared__ __align__(16) char smem[];
    const uint32_t sbase = (uint32_t)__cvta_generic_to_shared(smem);
    const int tid = threadIdx.x;
    const int bm = blockIdx.y, bn = blockIdx.x;
    const int nk = K >> 5;

    const __half* gA = A + (size_t)bm * 128 * K;
    const __half* gB = B + (size_t)bn * 128 * K;

    float acc[4][4][4];
    #pragma unroll
    for (int a = 0; a < 4; a++)
        #pragma unroll
        for (int b = 0; b < 4; b++)
            #pragma unroll
            for (int c = 0; c < 4; c++) acc[a][b][c] = 0.f;

    const int lr = tid >> 2, lc = (tid & 3) * 8;   // loader row/col

    auto load_stage = [&](int s, int kt) {
        uint32_t so = sbase + s * STAGE_BYTES;
        uint32_t dst = so + (uint32_t)(lr * SM_STRIDE + lc) * 2u;
        CP16(dst,             gA + (size_t)lr * K + kt * BK + lc);
        CP16(dst + ARR_BYTES, gB + (size_t)lr * K + kt * BK + lc);
        const int lr2 = lr + 64;
        uint32_t dst2 = so + (uint32_t)(lr2 * SM_STRIDE + lc) * 2u;
        CP16(dst2,             gA + (size_t)lr2 * K + kt * BK + lc);
        CP16(dst2 + ARR_BYTES, gB + (size_t)lr2 * K + kt * BK + lc);
    };

    const int wid = tid >> 5, lane = tid & 31;
    const int wm = (wid >> 2) << 6;   // 0 / 64
    const int wn = (wid & 3) << 5;    // 0..96

    auto compute = [&](int s) {
        uint32_t base = sbase + s * STAGE_BYTES;
        #pragma unroll
        for (int ks = 0; ks < 2; ks++) {
            uint32_t ah[4][4], bh[4][2];
            int arow = wm + (lane & 15);
            int acol = ks * 16 + (lane >> 4) * 8;
            #pragma unroll
            for (int mi = 0; mi < 4; mi++) {
                uint32_t ad = base + (uint32_t)(((arow + mi * 16) * SM_STRIDE + acol) << 1);
                LDSM4(ah[mi][0], ah[mi][1], ah[mi][2], ah[mi][3], ad);
            }
            int brow = wn + ((lane >> 4) & 1) * 8 + (lane & 7);
            int bcol = ks * 16 + ((lane >> 3) & 1) * 8;
            #pragma unroll
            for (int p = 0; p < 2; p++) {
                uint32_t bd = base + ARR_BYTES +
                              (uint32_t)(((brow + p * 16) * SM_STRIDE + bcol) << 1);
                uint32_t r0, r1, r2, r3;
                LDSM4(r0, r1, r2, r3, bd);
                bh[2 * p][0] = r0; bh[2 * p][1] = r1;
                bh[2 * p + 1][0] = r2; bh[2 * p + 1][1] = r3;
            }
            #pragma unroll
            for (int mi = 0; mi < 4; mi++)
                #pragma unroll
                for (int ni = 0; ni < 4; ni++)
                    MMA16816(acc[mi][ni], ah[mi], bh[ni][0], bh[ni][1]);
        }
    };

    load_stage(0, 0);
    asm volatile("cp.async.commit_group;");
    load_stage(1, 1);
    asm volatile("cp.async.commit_group;");
    for (int kt = 0; kt < nk; kt++) {
        if (kt + 2 < nk) load_stage((kt + 2) % 3, kt + 2);
        asm volatile("cp.async.commit_group;");
        asm volatile("cp.async.wait_group 2;");
        __syncthreads();
        compute(kt % 3);
        __syncthreads();
    }

    const int g = lane >> 2, tq = (lane & 3) * 2;
    #pragma unroll
    for (int mi = 0; mi < 4; mi++)
        #pragma unroll
        for (int ni = 0; ni < 4; ni++) {
            int row = bm * 128 + wm + mi * 16 + g;
            int col = bn * 128 + wn + ni * 8 + tq;
            if (OUT_HALF) {
                __half* C = (__half*)Cv;
                *reinterpret_cast<__half2*>(C + (size_t)row * Nn + col) =
                    __floats2half2_rn(acc[mi][ni][0], acc[mi][ni][1]);
                *reinterpret_cast<__half2*>(C + (size_t)(row + 8) * Nn + col) =
                    __floats2half2_rn(acc[mi][ni][2], acc[mi][ni][3]);
            } else {
                float* C = (float*)Cv;
                float2 r0 = *reinterpret_cast<const float2*>(R + (size_t)row * Nn + col);
                float2 r1 = *reinterpret_cast<const float2*>(R + (size_t)(row + 8) * Nn + col);
                *reinterpret_cast<float2*>(C + (size_t)row * Nn + col) =
                    make_float2(acc[mi][ni][0] + r0.x, acc[mi][ni][1] + r0.y);
                *reinterpret_cast<float2*>(C + (size_t)(row + 8) * Nn + col) =
                    make_float2(acc[mi][ni][2] + r1.x, acc[mi][ni][3] + r1.y);
            }
        }
}

// ---------------- elementwise kernels ----------------
__global__ __launch_bounds__(256) void f2h(const float* __restrict__ w,
                                           __half* __restrict__ h, int n) {
    int i = blockIdx.x * 256 + threadIdx.x;
    if (i < n) h[i] = __float2half(w[i]);
}

__global__ __launch_bounds__(256) void ln_half(
    const float* __restrict__ x, const float* __restrict__ gamma,
    const float* __restrict__ beta, __half* __restrict__ xh)
{
    int row = blockIdx.x, tid = threadIdx.x;
    const float4 v = reinterpret_cast<const float4*>(x + (size_t)row * D_MODEL)[tid];
    float s  = v.x + v.y + v.z + v.w;
    float ss = v.x*v.x + v.y*v.y + v.z*v.z + v.w*v.w;
    #pragma unroll
    for (int o = 16; o; o >>= 1) {
        s  += __shfl_xor_sync(0xffffffffu, s,  o);
        ss += __shfl_xor_sync(0xffffffffu, ss, o);
    }
    __shared__ float rs[8], rq[8], mv[2];
    int w = tid >> 5, lane = tid & 31;
    if (lane == 0) { rs[w] = s; rq[w] = ss; }
    __syncthreads();
    if (tid == 0) {
        float a = 0.f, b = 0.f;
        #pragma unroll
        for (int i = 0; i < 8; i++) { a += rs[i]; b += rq[i]; }
        float mu = a * (1.f / D_MODEL);
        float var = b * (1.f / D_MODEL) - mu * mu;
        mv[0] = mu; mv[1] = rsqrtf(var + LN_EPS);
    }
    __syncthreads();
    float mu = mv[0], rstd = mv[1];
    const float4 gv = reinterpret_cast<const float4*>(gamma)[tid];
    const float4 bv = reinterpret_cast<const float4*>(beta)[tid];
    __half2* out = (__half2*)(xh + (size_t)row * D_MODEL) + tid * 2;
    out[0] = __floats2half2_rn((v.x - mu) * rstd * gv.x + bv.x,
                               (v.y - mu) * rstd * gv.y + bv.y);
    out[1] = __floats2half2_rn((v.z - mu) * rstd * gv.z + bv.z,
                               (v.w - mu) * rstd * gv.w + bv.w);
}

// conv + gate over half2 (2 channels per thread)
__global__ __launch_bounds__(256) void conv_gate(
    const __half* __restrict__ xz, const float* __restrict__ cw,
    const float* __restrict__ cb, __half* __restrict__ y)
{
    int id = blockIdx.x * 256 + threadIdx.x;     // M_TOK * 1024 ids
    int cp = id & 1023;                          // channel pair
    int m  = id >> 10;
    int t  = m & 4095;
    int c  = cp * 2;
    size_t base = (size_t)m * N1 + c;
    float a0 = cb[c], a1 = cb[c + 1];
    #pragma unroll
    for (int j = 0; j < 4; j++) {
        if (t - 3 + j >= 0) {
            float2 xv = __half22float2(
                *reinterpret_cast<const __half2*>(xz + base - (size_t)(3 - j) * N1));
            a0 += cw[c * 4 + j] * xv.x;
            a1 += cw[(c + 1) * 4 + j] * xv.y;
        }
    }
    float2 zv = __half22float2(
        *reinterpret_cast<const __half2*>(xz + base + D_INNER));
    float s0 = a0 / (1.f + expf(-a0)) * (zv.x / (1.f + expf(-zv.x)));
    float s1 = a1 / (1.f + expf(-a1)) * (zv.y / (1.f + expf(-zv.y)));
    *reinterpret_cast<__half2*>(y + (size_t)m * D_INNER + c) =
        __floats2half2_rn(s0, s1);
}

extern "C" void kernel_launch(void* const* d_in, const int* in_sizes, int n_in,
                              void* d_out, int out_size)
{
    const float* x     = (const float*)d_in[0];
    const float* gamma = (const float*)d_in[1];
    const float* beta  = (const float*)d_in[2];
    const float* W_in  = (const float*)d_in[3];
    const float* cw    = (const float*)d_in[4];
    const float* cb    = (const float*)d_in[5];
    const float* W_out = (const float*)d_in[6];
    float* out = (float*)d_out;

    void *p_xn, *p_win, *p_wout, *p_xz, *p_y;
    cudaGetSymbolAddress(&p_xn,   g_xn);
    cudaGetSymbolAddress(&p_win,  g_win);
    cudaGetSymbolAddress(&p_wout, g_wout);
    cudaGetSymbolAddress(&p_xz,   g_xz);
    cudaGetSymbolAddress(&p_y,    g_y);

    cudaFuncSetAttribute(gemm_f16<true>,
        cudaFuncAttributeMaxDynamicSharedMemorySize, SMEM_DYN);
    cudaFuncSetAttribute(gemm_f16<false>,
        cudaFuncAttributeMaxDynamicSharedMemorySize, SMEM_DYN);

    f2h<<<(N1 * K1 + 255) / 256, 256>>>(W_in,  (__half*)p_win,  N1 * K1);
    f2h<<<(N2 * K2 + 255) / 256, 256>>>(W_out, (__half*)p_wout, N2 * K2);
    ln_half<<<M_TOK, 256>>>(x, gamma, beta, (__half*)p_xn);

    dim3 g1(N1 / 128, M_TOK / 128);
    gemm_f16<true><<<g1, 256, SMEM_DYN>>>((const __half*)p_xn,
        (const __half*)p_win, p_xz, nullptr, K1, N1);

    conv_gate<<<(M_TOK * 1024) / 256, 256>>>((const __half*)p_xz, cw, cb,
        (__half*)p_y);

    dim3 g2(N2 / 128, M_TOK / 128);
    gemm_f16<false><<<g2, 256, SMEM_DYN>>>((const __half*)p_y,
        (const __half*)p_wout, out, x, K2, N2);
}

// round 6
// speedup vs baseline: 2.5253x; 1.0605x over previous
#include <cuda_runtime.h>
#include <cuda_fp16.h>
#include <math.h>
#include <stdint.h>

#define D_MODEL 1024
#define D_INNER 2048
#define M_TOK   16384
#define N1      4096
#define K1      1024
#define N2      1024
#define K2      2048
#define LN_EPS  1e-5f

__device__ __half g_xn  [(size_t)M_TOK * K1];
__device__ __half g_win [(size_t)N1 * K1];
__device__ __half g_wout[(size_t)N2 * K2];
__device__ __half g_xz  [(size_t)M_TOK * N1];
__device__ __half g_y   [(size_t)M_TOK * K2];

// ---------------- fp16 GEMM: C[M,N] = A[M,K] * B[N,K]^T ----------------
// 128x128x32 tiles, 256 thr (8 warps 2x4, warp 64x32), 4-stage cp.async,
// ONE sync per k-iter, ldmatrix stride-40 (conflict-free), f32 accum.
#define BK          32
#define SM_STRIDE   40
#define ARR_BYTES   (128 * SM_STRIDE * 2)   // 10240
#define STAGE_BYTES (2 * ARR_BYTES)         // 20480
#define NSTAGE      4
#define SMEM_DYN    (NSTAGE * STAGE_BYTES)  // 81920

#define LDSM4(R0, R1, R2, R3, ADDR)                                          \
    asm volatile("ldmatrix.sync.aligned.m8n8.x4.shared.b16 {%0,%1,%2,%3},[%4];" \
                 : "=r"(R0), "=r"(R1), "=r"(R2), "=r"(R3) : "r"(ADDR))
#define MMA16816(C, A, B0, B1)                                               \
    asm volatile("mma.sync.aligned.m16n8k16.row.col.f32.f16.f16.f32 "         \
                 "{%0,%1,%2,%3},{%4,%5,%6,%7},{%8,%9},{%0,%1,%2,%3};"         \
                 : "+f"((C)[0]), "+f"((C)[1]), "+f"((C)[2]), "+f"((C)[3])     \
                 : "r"((A)[0]), "r"((A)[1]), "r"((A)[2]), "r"((A)[3]),        \
                   "r"(B0), "r"(B1))
#define CP16(dst, src) \
    asm volatile("cp.async.cg.shared.global [%0], [%1], 16;" :: "r"(dst), "l"(src))

template <bool OUT_HALF>
__global__ __launch_bounds__(256, 2) void gemm_f16(
    const __half* __restrict__ A, const __half* __restrict__ B,
    void* __restrict__ Cv, const float* __restrict__ R, int K, int Nn)
{
    extern __shared__ __align__(16) char smem[];
    const uint32_t sbase = (uint32_t)__cvta_generic_to_shared(smem);
    const int tid = threadIdx.x;
    const int bm = blockIdx.y, bn = blockIdx.x;
    const int nk = K >> 5;

    const __half* gA = A + (size_t)bm * 128 * K;
    const __half* gB = B + (size_t)bn * 128 * K;

    float acc[4][4][4];
    #pragma unroll
    for (int a = 0; a < 4; a++)
        #pragma unroll
        for (int b = 0; b < 4; b++)
            #pragma unroll
            for (int c = 0; c < 4; c++) acc[a][b][c] = 0.f;

    const int lr = tid >> 2, lc = (tid & 3) * 8;

    auto load_stage = [&](int s, int kt) {
        uint32_t so = sbase + s * STAGE_BYTES;
        uint32_t dst = so + (uint32_t)(lr * SM_STRIDE + lc) * 2u;
        CP16(dst,             gA + (size_t)lr * K + kt * BK + lc);
        CP16(dst + ARR_BYTES, gB + (size_t)lr * K + kt * BK + lc);
        const int lr2 = lr + 64;
        uint32_t dst2 = so + (uint32_t)(lr2 * SM_STRIDE + lc) * 2u;
        CP16(dst2,             gA + (size_t)lr2 * K + kt * BK + lc);
        CP16(dst2 + ARR_BYTES, gB + (size_t)lr2 * K + kt * BK + lc);
    };

    const int wid = tid >> 5, lane = tid & 31;
    const int wm = (wid >> 2) << 6;
    const int wn = (wid & 3) << 5;

    auto compute = [&](int s) {
        uint32_t base = sbase + s * STAGE_BYTES;
        #pragma unroll
        for (int ks = 0; ks < 2; ks++) {
            uint32_t ah[4][4], bh[4][2];
            int arow = wm + (lane & 15);
            int acol = ks * 16 + (lane >> 4) * 8;
            #pragma unroll
            for (int mi = 0; mi < 4; mi++) {
                uint32_t ad = base + (uint32_t)(((arow + mi * 16) * SM_STRIDE + acol) << 1);
                LDSM4(ah[mi][0], ah[mi][1], ah[mi][2], ah[mi][3], ad);
            }
            int brow = wn + ((lane >> 4) & 1) * 8 + (lane & 7);
            int bcol = ks * 16 + ((lane >> 3) & 1) * 8;
            #pragma unroll
            for (int p = 0; p < 2; p++) {
                uint32_t bd = base + ARR_BYTES +
                              (uint32_t)(((brow + p * 16) * SM_STRIDE + bcol) << 1);
                uint32_t r0, r1, r2, r3;
                LDSM4(r0, r1, r2, r3, bd);
                bh[2 * p][0] = r0; bh[2 * p][1] = r1;
                bh[2 * p + 1][0] = r2; bh[2 * p + 1][1] = r3;
            }
            #pragma unroll
            for (int mi = 0; mi < 4; mi++)
                #pragma unroll
                for (int ni = 0; ni < 4; ni++)
                    MMA16816(acc[mi][ni], ah[mi], bh[ni][0], bh[ni][1]);
        }
    };

    // prefetch 3 stages
    #pragma unroll
    for (int p = 0; p < 3; p++) {
        load_stage(p, p);
        asm volatile("cp.async.commit_group;");
    }

    for (int kt = 0; kt < nk; kt++) {
        asm volatile("cp.async.wait_group 2;");
        __syncthreads();
        if (kt + 3 < nk) load_stage((kt + 3) & 3, kt + 3);
        asm volatile("cp.async.commit_group;");
        compute(kt & 3);
    }

    const int g = lane >> 2, tq = (lane & 3) * 2;
    #pragma unroll
    for (int mi = 0; mi < 4; mi++)
        #pragma unroll
        for (int ni = 0; ni < 4; ni++) {
            int row = bm * 128 + wm + mi * 16 + g;
            int col = bn * 128 + wn + ni * 8 + tq;
            if (OUT_HALF) {
                __half* C = (__half*)Cv;
                *reinterpret_cast<__half2*>(C + (size_t)row * Nn + col) =
                    __floats2half2_rn(acc[mi][ni][0], acc[mi][ni][1]);
                *reinterpret_cast<__half2*>(C + (size_t)(row + 8) * Nn + col) =
                    __floats2half2_rn(acc[mi][ni][2], acc[mi][ni][3]);
            } else {
                float* C = (float*)Cv;
                float2 r0 = *reinterpret_cast<const float2*>(R + (size_t)row * Nn + col);
                float2 r1 = *reinterpret_cast<const float2*>(R + (size_t)(row + 8) * Nn + col);
                *reinterpret_cast<float2*>(C + (size_t)row * Nn + col) =
                    make_float2(acc[mi][ni][0] + r0.x, acc[mi][ni][1] + r0.y);
                *reinterpret_cast<float2*>(C + (size_t)(row + 8) * Nn + col) =
                    make_float2(acc[mi][ni][2] + r1.x, acc[mi][ni][3] + r1.y);
            }
        }
}

// ---------------- elementwise ----------------
__global__ __launch_bounds__(256) void f2h(const float* __restrict__ w,
                                           __half* __restrict__ h, int n) {
    int i = blockIdx.x * 256 + threadIdx.x;
    if (i < n) h[i] = __float2half(w[i]);
}

__global__ __launch_bounds__(256) void ln_half(
    const float* __restrict__ x, const float* __restrict__ gamma,
    const float* __restrict__ beta, __half* __restrict__ xh)
{
    int row = blockIdx.x, tid = threadIdx.x;
    const float4 v = reinterpret_cast<const float4*>(x + (size_t)row * D_MODEL)[tid];
    float s  = v.x + v.y + v.z + v.w;
    float ss = v.x*v.x + v.y*v.y + v.z*v.z + v.w*v.w;
    #pragma unroll
    for (int o = 16; o; o >>= 1) {
        s  += __shfl_xor_sync(0xffffffffu, s,  o);
        ss += __shfl_xor_sync(0xffffffffu, ss, o);
    }
    __shared__ float rs[8], rq[8], mv[2];
    int w = tid >> 5, lane = tid & 31;
    if (lane == 0) { rs[w] = s; rq[w] = ss; }
    __syncthreads();
    if (tid == 0) {
        float a = 0.f, b = 0.f;
        #pragma unroll
        for (int i = 0; i < 8; i++) { a += rs[i]; b += rq[i]; }
        float mu = a * (1.f / D_MODEL);
        float var = b * (1.f / D_MODEL) - mu * mu;
        mv[0] = mu; mv[1] = rsqrtf(var + LN_EPS);
    }
    __syncthreads();
    float mu = mv[0], rstd = mv[1];
    const float4 gv = reinterpret_cast<const float4*>(gamma)[tid];
    const float4 bv = reinterpret_cast<const float4*>(beta)[tid];
    __half2* out = (__half2*)(xh + (size_t)row * D_MODEL) + tid * 2;
    out[0] = __floats2half2_rn((v.x - mu) * rstd * gv.x + bv.x,
                               (v.y - mu) * rstd * gv.y + bv.y);
    out[1] = __floats2half2_rn((v.z - mu) * rstd * gv.z + bv.z,
                               (v.w - mu) * rstd * gv.w + bv.w);
}

__global__ __launch_bounds__(256) void conv_gate(
    const __half* __restrict__ xz, const float* __restrict__ cw,
    const float* __restrict__ cb, __half* __restrict__ y)
{
    int id = blockIdx.x * 256 + threadIdx.x;
    int cp = id & 1023;
    int m  = id >> 10;
    int t  = m & 4095;
    int c  = cp * 2;
    size_t base = (size_t)m * N1 + c;
    float a0 = cb[c], a1 = cb[c + 1];
    #pragma unroll
    for (int j = 0; j < 4; j++) {
        if (t - 3 + j >= 0) {
            float2 xv = __half22float2(
                *reinterpret_cast<const __half2*>(xz + base - (size_t)(3 - j) * N1));
            a0 += cw[c * 4 + j] * xv.x;
            a1 += cw[(c + 1) * 4 + j] * xv.y;
        }
    }
    float2 zv = __half22float2(
        *reinterpret_cast<const __half2*>(xz + base + D_INNER));
    float s0 = a0 / (1.f + expf(-a0)) * (zv.x / (1.f + expf(-zv.x)));
    float s1 = a1 / (1.f + expf(-a1)) * (zv.y / (1.f + expf(-zv.y)));
    *reinterpret_cast<__half2*>(y + (size_t)m * D_INNER + c) =
        __floats2half2_rn(s0, s1);
}

extern "C" void kernel_launch(void* const* d_in, const int* in_sizes, int n_in,
                              void* d_out, int out_size)
{
    const float* x     = (const float*)d_in[0];
    const float* gamma = (const float*)d_in[1];
    const float* beta  = (const float*)d_in[2];
    const float* W_in  = (const float*)d_in[3];
    const float* cw    = (const float*)d_in[4];
    const float* cb    = (const float*)d_in[5];
    const float* W_out = (const float*)d_in[6];
    float* out = (float*)d_out;

    void *p_xn, *p_win, *p_wout, *p_xz, *p_y;
    cudaGetSymbolAddress(&p_xn,   g_xn);
    cudaGetSymbolAddress(&p_win,  g_win);
    cudaGetSymbolAddress(&p_wout, g_wout);
    cudaGetSymbolAddress(&p_xz,   g_xz);
    cudaGetSymbolAddress(&p_y,    g_y);

    cudaFuncSetAttribute(gemm_f16<true>,
        cudaFuncAttributeMaxDynamicSharedMemorySize, SMEM_DYN);
    cudaFuncSetAttribute(gemm_f16<false>,
        cudaFuncAttributeMaxDynamicSharedMemorySize, SMEM_DYN);

    f2h<<<(N1 * K1 + 255) / 256, 256>>>(W_in,  (__half*)p_win,  N1 * K1);
    f2h<<<(N2 * K2 + 255) / 256, 256>>>(W_out, (__half*)p_wout, N2 * K2);
    ln_half<<<M_TOK, 256>>>(x, gamma, beta, (__half*)p_xn);

    dim3 g1(N1 / 128, M_TOK / 128);
    gemm_f16<true><<<g1, 256, SMEM_DYN>>>((const __half*)p_xn,
        (const __half*)p_win, p_xz, nullptr, K1, N1);

    conv_gate<<<(M_TOK * 1024) / 256, 256>>>((const __half*)p_xz, cw, cb,
        (__half*)p_y);

    dim3 g2(N2 / 128, M_TOK / 128);
    gemm_f16<false><<<g2, 256, SMEM_DYN>>>((const __half*)p_y,
        (const __half*)p_wout, out, x, K2, N2);
}

// round 7
// speedup vs baseline: 2.8961x; 1.1468x over previous
#include <cuda_runtime.h>
#include <cuda_fp16.h>
#include <math.h>
#include <stdint.h>

#define D_MODEL 1024
#define D_INNER 2048
#define M_TOK   16384
#define N1      4096
#define K1      1024
#define N2      1024
#define K2      2048
#define LN_EPS  1e-5f

__device__ __half g_xn  [(size_t)M_TOK * K1];
__device__ __half g_win [(size_t)N1 * K1];
__device__ __half g_wout[(size_t)N2 * K2];
__device__ __half g_xz  [(size_t)M_TOK * N1];
__device__ __half g_y   [(size_t)M_TOK * K2];

// ---- fp16 GEMM: C[M,N] = A[M,K] * B[N,K]^T, 128x128x32, 128 thr,
//      4 warps x (64x64 warp tile), 4-stage cp.async, 1 sync/iter ----
#define BK          32
#define SM_STRIDE   40
#define ARR_BYTES   (128 * SM_STRIDE * 2)   // 10240
#define STAGE_BYTES (2 * ARR_BYTES)         // 20480
#define NSTAGE      4
#define SMEM_DYN    (NSTAGE * STAGE_BYTES)  // 81920

#define LDSM4(R0, R1, R2, R3, ADDR)                                          \
    asm volatile("ldmatrix.sync.aligned.m8n8.x4.shared.b16 {%0,%1,%2,%3},[%4];" \
                 : "=r"(R0), "=r"(R1), "=r"(R2), "=r"(R3) : "r"(ADDR))
#define MMA16816(C, A, B0, B1)                                               \
    asm volatile("mma.sync.aligned.m16n8k16.row.col.f32.f16.f16.f32 "         \
                 "{%0,%1,%2,%3},{%4,%5,%6,%7},{%8,%9},{%0,%1,%2,%3};"         \
                 : "+f"((C)[0]), "+f"((C)[1]), "+f"((C)[2]), "+f"((C)[3])     \
                 : "r"((A)[0]), "r"((A)[1]), "r"((A)[2]), "r"((A)[3]),        \
                   "r"(B0), "r"(B1))
#define CP16(dst, src) \
    asm volatile("cp.async.cg.shared.global [%0], [%1], 16;" :: "r"(dst), "l"(src))

template <bool OUT_HALF>
__global__ __launch_bounds__(128, 2) void gemm_f16(
    const __half* __restrict__ A, const __half* __restrict__ B,
    void* __restrict__ Cv, const float* __restrict__ R, int K, int Nn)
{
    extern __shared__ __align__(16) char smem[];
    const uint32_t sbase = (uint32_t)__cvta_generic_to_shared(smem);
    const int tid = threadIdx.x;
    const int bm = blockIdx.y, bn = blockIdx.x;
    const int nk = K >> 5;

    const __half* gA = A + (size_t)bm * 128 * K;
    const __half* gB = B + (size_t)bn * 128 * K;

    float acc[4][8][4];
    #pragma unroll
    for (int a = 0; a < 4; a++)
        #pragma unroll
        for (int b = 0; b < 8; b++)
            #pragma unroll
            for (int c = 0; c < 4; c++) acc[a][b][c] = 0.f;

    const int lr = tid >> 2, lc = (tid & 3) * 8;   // 32 rows x 4 chunks

    auto load_stage = [&](int s, int kt) {
        uint32_t so = sbase + s * STAGE_BYTES;
        #pragma unroll
        for (int i = 0; i < 4; i++) {
            int r = i * 32 + lr;
            uint32_t dst = so + (uint32_t)(r * SM_STRIDE + lc) * 2u;
            CP16(dst,             gA + (size_t)r * K + kt * BK + lc);
            CP16(dst + ARR_BYTES, gB + (size_t)r * K + kt * BK + lc);
        }
    };

    const int wid = tid >> 5, lane = tid & 31;
    const int wm = (wid >> 1) << 6;   // 0 / 64
    const int wn = (wid & 1) << 6;    // 0 / 64

    auto compute = [&](int s) {
        uint32_t base = sbase + s * STAGE_BYTES;
        #pragma unroll
        for (int ks = 0; ks < 2; ks++) {
            uint32_t ah[4][4], bh[8][2];
            int arow = wm + (lane & 15);
            int acol = ks * 16 + (lane >> 4) * 8;
            #pragma unroll
            for (int mi = 0; mi < 4; mi++) {
                uint32_t ad = base + (uint32_t)(((arow + mi * 16) * SM_STRIDE + acol) << 1);
                LDSM4(ah[mi][0], ah[mi][1], ah[mi][2], ah[mi][3], ad);
            }
            int brow = wn + ((lane >> 4) & 1) * 8 + (lane & 7);
            int bcol = ks * 16 + ((lane >> 3) & 1) * 8;
            #pragma unroll
            for (int p = 0; p < 4; p++) {
                uint32_t bd = base + ARR_BYTES +
                              (uint32_t)(((brow + p * 16) * SM_STRIDE + bcol) << 1);
                uint32_t r0, r1, r2, r3;
                LDSM4(r0, r1, r2, r3, bd);
                bh[2 * p][0] = r0; bh[2 * p][1] = r1;
                bh[2 * p + 1][0] = r2; bh[2 * p + 1][1] = r3;
            }
            #pragma unroll
            for (int mi = 0; mi < 4; mi++)
                #pragma unroll
                for (int ni = 0; ni < 8; ni++)
                    MMA16816(acc[mi][ni], ah[mi], bh[ni][0], bh[ni][1]);
        }
    };

    #pragma unroll
    for (int p = 0; p < 3; p++) {
        load_stage(p, p);
        asm volatile("cp.async.commit_group;");
    }
    for (int kt = 0; kt < nk; kt++) {
        asm volatile("cp.async.wait_group 2;");
        __syncthreads();
        if (kt + 3 < nk) load_stage((kt + 3) & 3, kt + 3);
        asm volatile("cp.async.commit_group;");
        compute(kt & 3);
    }

    const int g = lane >> 2, tq = (lane & 3) * 2;
    #pragma unroll
    for (int mi = 0; mi < 4; mi++)
        #pragma unroll
        for (int ni = 0; ni < 8; ni++) {
            int row = bm * 128 + wm + mi * 16 + g;
            int col = bn * 128 + wn + ni * 8 + tq;
            if (OUT_HALF) {
                __half* C = (__half*)Cv;
                *reinterpret_cast<__half2*>(C + (size_t)row * Nn + col) =
                    __floats2half2_rn(acc[mi][ni][0], acc[mi][ni][1]);
                *reinterpret_cast<__half2*>(C + (size_t)(row + 8) * Nn + col) =
                    __floats2half2_rn(acc[mi][ni][2], acc[mi][ni][3]);
            } else {
                float* C = (float*)Cv;
                float2 r0 = *reinterpret_cast<const float2*>(R + (size_t)row * Nn + col);
                float2 r1 = *reinterpret_cast<const float2*>(R + (size_t)(row + 8) * Nn + col);
                *reinterpret_cast<float2*>(C + (size_t)row * Nn + col) =
                    make_float2(acc[mi][ni][0] + r0.x, acc[mi][ni][1] + r0.y);
                *reinterpret_cast<float2*>(C + (size_t)(row + 8) * Nn + col) =
                    make_float2(acc[mi][ni][2] + r1.x, acc[mi][ni][3] + r1.y);
            }
        }
}

// ---------------- elementwise ----------------
__global__ __launch_bounds__(256) void f2h(const float* __restrict__ w,
                                           __half* __restrict__ h, int n) {
    int i = blockIdx.x * 256 + threadIdx.x;
    if (i < n) h[i] = __float2half(w[i]);
}

__global__ __launch_bounds__(256) void ln_half(
    const float* __restrict__ x, const float* __restrict__ gamma,
    const float* __restrict__ beta, __half* __restrict__ xh)
{
    int row = blockIdx.x, tid = threadIdx.x;
    const float4 v = reinterpret_cast<const float4*>(x + (size_t)row * D_MODEL)[tid];
    float s  = v.x + v.y + v.z + v.w;
    float ss = v.x*v.x + v.y*v.y + v.z*v.z + v.w*v.w;
    #pragma unroll
    for (int o = 16; o; o >>= 1) {
        s  += __shfl_xor_sync(0xffffffffu, s,  o);
        ss += __shfl_xor_sync(0xffffffffu, ss, o);
    }
    __shared__ float rs[8], rq[8], mv[2];
    int w = tid >> 5, lane = tid & 31;
    if (lane == 0) { rs[w] = s; rq[w] = ss; }
    __syncthreads();
    if (tid == 0) {
        float a = 0.f, b = 0.f;
        #pragma unroll
        for (int i = 0; i < 8; i++) { a += rs[i]; b += rq[i]; }
        float mu = a * (1.f / D_MODEL);
        float var = b * (1.f / D_MODEL) - mu * mu;
        mv[0] = mu; mv[1] = rsqrtf(var + LN_EPS);
    }
    __syncthreads();
    float mu = mv[0], rstd = mv[1];
    const float4 gv = reinterpret_cast<const float4*>(gamma)[tid];
    const float4 bv = reinterpret_cast<const float4*>(beta)[tid];
    __half2* out = (__half2*)(xh + (size_t)row * D_MODEL) + tid * 2;
    out[0] = __floats2half2_rn((v.x - mu) * rstd * gv.x + bv.x,
                               (v.y - mu) * rstd * gv.y + bv.y);
    out[1] = __floats2half2_rn((v.z - mu) * rstd * gv.z + bv.z,
                               (v.w - mu) * rstd * gv.w + bv.w);
}

__global__ __launch_bounds__(256) void conv_gate(
    const __half* __restrict__ xz, const float* __restrict__ cw,
    const float* __restrict__ cb, __half* __restrict__ y)
{
    int id = blockIdx.x * 256 + threadIdx.x;
    int cp = id & 1023;
    int m  = id >> 10;
    int t  = m & 4095;
    int c  = cp * 2;
    size_t base = (size_t)m * N1 + c;
    float a0 = cb[c], a1 = cb[c + 1];
    #pragma unroll
    for (int j = 0; j < 4; j++) {
        if (t - 3 + j >= 0) {
            float2 xv = __half22float2(
                *reinterpret_cast<const __half2*>(xz + base - (size_t)(3 - j) * N1));
            a0 += cw[c * 4 + j] * xv.x;
            a1 += cw[(c + 1) * 4 + j] * xv.y;
        }
    }
    float2 zv = __half22float2(
        *reinterpret_cast<const __half2*>(xz + base + D_INNER));
    float s0 = a0 / (1.f + expf(-a0)) * (zv.x / (1.f + expf(-zv.x)));
    float s1 = a1 / (1.f + expf(-a1)) * (zv.y / (1.f + expf(-zv.y)));
    *reinterpret_cast<__half2*>(y + (size_t)m * D_INNER + c) =
        __floats2half2_rn(s0, s1);
}

extern "C" void kernel_launch(void* const* d_in, const int* in_sizes, int n_in,
                              void* d_out, int out_size)
{
    const float* x     = (const float*)d_in[0];
    const float* gamma = (const float*)d_in[1];
    const float* beta  = (const float*)d_in[2];
    const float* W_in  = (const float*)d_in[3];
    const float* cw    = (const float*)d_in[4];
    const float* cb    = (const float*)d_in[5];
    const float* W_out = (const float*)d_in[6];
    float* out = (float*)d_out;

    void *p_xn, *p_win, *p_wout, *p_xz, *p_y;
    cudaGetSymbolAddress(&p_xn,   g_xn);
    cudaGetSymbolAddress(&p_win,  g_win);
    cudaGetSymbolAddress(&p_wout, g_wout);
    cudaGetSymbolAddress(&p_xz,   g_xz);
    cudaGetSymbolAddress(&p_y,    g_y);

    cudaFuncSetAttribute(gemm_f16<true>,
        cudaFuncAttributeMaxDynamicSharedMemorySize, SMEM_DYN);
    cudaFuncSetAttribute(gemm_f16<false>,
        cudaFuncAttributeMaxDynamicSharedMemorySize, SMEM_DYN);

    f2h<<<(N1 * K1 + 255) / 256, 256>>>(W_in,  (__half*)p_win,  N1 * K1);
    f2h<<<(N2 * K2 + 255) / 256, 256>>>(W_out, (__half*)p_wout, N2 * K2);
    ln_half<<<M_TOK, 256>>>(x, gamma, beta, (__half*)p_xn);

    dim3 g1(N1 / 128, M_TOK / 128);
    gemm_f16<true><<<g1, 128, SMEM_DYN>>>((const __half*)p_xn,
        (const __half*)p_win, p_xz, nullptr, K1, N1);

    conv_gate<<<(M_TOK * 1024) / 256, 256>>>((const __half*)p_xz, cw, cb,
        (__half*)p_y);

    dim3 g2(N2 / 128, M_TOK / 128);
    gemm_f16<false><<<g2, 128, SMEM_DYN>>>((const __half*)p_y,
        (const __half*)p_wout, out, x, K2, N2);
}